// round 10
// baseline (speedup 1.0000x reference)
#include <cuda_runtime.h>

#define MAP_W  64
#define MAP_H  64
#define T_SIZE 64
#define NUM_CP 8
#define BATCH  128
#define XPB    2      // x-columns per block

__device__ __forceinline__ float ex2_approx(float x) {
    float r;
    asm("ex2.approx.f32 %0, %1;" : "=f"(r) : "f"(x));
    return r;
}

// Fused kernel: block = (b, pair of x columns). Threads 0..63 compute the
// per-(b,t) Gaussian params for all 64 t into shared memory (SoA layout),
// then all 256 threads stream 2 * 64*64 (y,t) tiles of exp2 evaluations.
// Thread mapping in the streaming phase: lane (0..31) owns 2 consecutive t
// (float2 store, 256B contiguous per warp), threadIdx.y (0..7) strides y.
// This halves the live register state vs the 4-t/thread variant (48 regs,
// 5 CTAs/SM) to lift occupancy without forcing a bound (R8 showed forced
// caps spill).
//
// exponent(dx,dy) = al*dx^2 + be*dx*dy + ga*dy^2 + f0  (log2 domain; f0
// includes log2 of the normalizer), output = exp2(exponent).
struct SoAParams {
    float mx[T_SIZE], my[T_SIZE], al[T_SIZE],
          be[T_SIZE], ga[T_SIZE], f0[T_SIZE];
};

__global__ __launch_bounds__(256)
void map_kernel(const float* __restrict__ cp_means,
                const int*   __restrict__ num_cps,
                const float* __restrict__ cp_cov,
                float*       __restrict__ out) {
    __shared__ SoAParams sp;

    int x0  = blockIdx.x * XPB;                // 0,2,..,62
    int b   = blockIdx.y;                      // 0..127
    int tid = threadIdx.y * 32 + threadIdx.x;  // 0..255

    if (tid < T_SIZE) {
        int   t  = tid;
        float tf = (float)t * (1.0f / 63.0f);
        float u  = 1.0f - tf;
        int   n  = __ldg(num_cps + b) - 1;     // 2..7

        // Bernstein weights via de Casteljau (exact, register-resident).
        float w[NUM_CP];
        w[0] = 1.0f;
        #pragma unroll
        for (int k = 1; k < NUM_CP; ++k) w[k] = 0.0f;
        #pragma unroll
        for (int m = 1; m < NUM_CP; ++m) {
            if (m <= n) {
                #pragma unroll
                for (int k = NUM_CP - 1; k >= 1; --k)
                    w[k] = u * w[k] + tf * w[k - 1];
                w[0] = u * w[0];
            }
        }

        float mx = 0.f, my = 0.f, cxx = 0.f, cxy = 0.f, cyx = 0.f, cyy = 0.f;
        #pragma unroll
        for (int k = 0; k < NUM_CP; ++k) {
            float wk = w[k];
            float2 m = __ldg((const float2*)(cp_means + (k * BATCH + b) * 2));
            mx += wk * m.x;
            my += wk * m.y;
            float w2 = wk * wk;
            float4 cv = __ldg((const float4*)(cp_cov + (k * BATCH + b) * 4));
            cxx += w2 * cv.x;  cxy += w2 * cv.y;
            cyx += w2 * cv.z;  cyy += w2 * cv.w;
        }

        float det  = cxx * cyy - cxy * cyx;
        float invd = 1.0f / det;
        const float L = 1.4426950408889634f;   // log2(e)
        sp.mx[t] = mx;
        sp.my[t] = my;
        sp.al[t] = -0.5f * L * cyy * invd;
        sp.be[t] =  0.5f * L * (cxy + cyx) * invd;
        sp.ga[t] = -0.5f * L * cxx * invd;
        sp.f0[t] = -log2f(6.283185307179586f * sqrtf(det));
    }
    __syncthreads();

    int lane = threadIdx.x;   // 0..31 : t-pair (2 consecutive t)
    int wy   = threadIdx.y;   // 0..7  : y stripe

    // Conflict-free float2 loads: lane addresses are consecutive 8B chunks.
    float2 mx2 = *(const float2*)&sp.mx[2 * lane];
    float2 my2 = *(const float2*)&sp.my[2 * lane];
    float2 al2 = *(const float2*)&sp.al[2 * lane];
    float2 be2 = *(const float2*)&sp.be[2 * lane];
    float2 ga2 = *(const float2*)&sp.ga[2 * lane];
    float2 f02 = *(const float2*)&sp.f0[2 * lane];

    // Per-column constants: Q = be*dx, P = al*dx^2 + f0
    float Q[XPB][2], P[XPB][2];
    #pragma unroll
    for (int xi = 0; xi < XPB; ++xi) {
        float xf  = (float)(x0 + xi);
        float dx0 = xf - mx2.x;
        float dx1 = xf - mx2.y;
        Q[xi][0] = be2.x * dx0;
        Q[xi][1] = be2.y * dx1;
        P[xi][0] = fmaf(al2.x * dx0, dx0, f02.x);
        P[xi][1] = fmaf(al2.y * dx1, dx1, f02.y);
    }

    // Output base in float2 units: (((b*64 + x0)*64 + y)*64 + 2*lane)/2
    float2* ob0 = (float2*)out
                + (size_t)((b * MAP_W + x0) * MAP_H) * (T_SIZE / 2) + lane;

    #pragma unroll
    for (int xi = 0; xi < XPB; ++xi) {
        float2* ob = ob0 + (size_t)xi * MAP_H * (T_SIZE / 2);
        #pragma unroll
        for (int i = 0; i < 8; ++i) {
            int   yy = wy + 8 * i;
            float yf = (float)yy;
            float2 r;
            {
                float dy = yf - my2.x;
                r.x = ex2_approx(fmaf(dy, fmaf(ga2.x, dy, Q[xi][0]), P[xi][0]));
            }
            {
                float dy = yf - my2.y;
                r.y = ex2_approx(fmaf(dy, fmaf(ga2.y, dy, Q[xi][1]), P[xi][1]));
            }
            __stcs(ob + (size_t)yy * (T_SIZE / 2), r);
        }
    }
}

extern "C" void kernel_launch(void* const* d_in, const int* in_sizes, int n_in,
                              void* d_out, int out_size) {
    const float* cp_means = (const float*)d_in[0];
    const int*   num_cps  = (const int*)d_in[1];
    const float* cp_cov   = (const float*)d_in[2];
    float*       out      = (float*)d_out;

    dim3 block(32, 8);
    dim3 grid(MAP_W / XPB, BATCH);
    map_kernel<<<grid, block>>>(cp_means, num_cps, cp_cov, out);
}